// round 6
// baseline (speedup 1.0000x reference)
#include <cuda_runtime.h>
#include <cuda_fp16.h>
#include <math.h>
#include <cstdint>

#define CN 8192
#define CD 128
#define CV 3

#define TM 128            // n rows per CTA tile
#define TN 64             // m cols per tile
#define NTILES (CN / TM)  // 64
#define MTILES (CN / TN)  // 128
#define TOTAL_JOBS (NTILES * MTILES)  // 8192

// fp8 smem tiles: 128 bytes payload per row + 16 pad = 144 (conflict-free 4B lane loads)
#define RS8 144
#define A_OFF 0
#define A_BYTES (TM * RS8)                    // 18432
#define B_OFF A_BYTES
#define B_VIEW_BYTES (TN * RS8)               // 9216
#define B_BUF_BYTES (CV * B_VIEW_BYTES)       // 27648
#define NBUF 3
#define SMEM_TOTAL (B_OFF + NBUF * B_BUF_BYTES)  // 101376

#define K2LOG2E 2.8853900817779268  /* 2/ln2 : exp(2*sim) = 2^(sim*K2) */
#define LN2F 0.6931471805599453f

// ---- device scratch ----
__device__ __align__(256) uint8_t g_Hc8[CN * CD];        // e4m3, pre-scaled by 2/ln2
__device__ __align__(256) uint8_t g_Hv8[CV * CN * CD];   // e4m3
__device__ __align__(256) __half g_Hc16[CN * CD];        // fp16, pre-scaled (finalize)
__device__ __align__(256) __half g_Hv16[CV * CN * CD];   // fp16 (finalize)
__device__ __align__(256) float g_denom[CV * CN];
__device__ double g_loss;

// ---------------- helpers ----------------
__device__ __forceinline__ uint32_t smem_u32(const void* p) {
    uint32_t a;
    asm("{ .reg .u64 t; cvta.to.shared.u64 t, %1; cvt.u32.u64 %0, t; }" : "=r"(a) : "l"(p));
    return a;
}
__device__ __forceinline__ void cp_async16(uint32_t dst, const void* src) {
    asm volatile("cp.async.cg.shared.global [%0], [%1], 16;" :: "r"(dst), "l"(src));
}
#define CP_COMMIT() asm volatile("cp.async.commit_group;" ::: "memory")
#define CP_WAIT0()  asm volatile("cp.async.wait_group 0;" ::: "memory")
#define CP_WAIT1()  asm volatile("cp.async.wait_group 1;" ::: "memory")

// fp8 e4m3 MMA, fp32 accumulate: D[16x8] += A[16x32] * B[32x8]
__device__ __forceinline__ void mma_fp8(float* c, const uint32_t* a, uint32_t b0, uint32_t b1) {
    asm volatile(
        "mma.sync.aligned.m16n8k32.row.col.f32.e4m3.e4m3.f32 "
        "{%0,%1,%2,%3}, {%4,%5,%6,%7}, {%8,%9}, {%0,%1,%2,%3};"
        : "+f"(c[0]), "+f"(c[1]), "+f"(c[2]), "+f"(c[3])
        : "r"(a[0]), "r"(a[1]), "r"(a[2]), "r"(a[3]), "r"(b0), "r"(b1));
}
__device__ __forceinline__ float ex2f(float x) {
    float r;
    asm("ex2.approx.f32 %0, %1;" : "=f"(r) : "f"(x));
    return r;
}
__device__ __forceinline__ uint8_t f2e4m3(float x) {
    uint16_t r;
    asm("cvt.rn.satfinite.e4m3x2.f32 %0, %1, %2;" : "=h"(r) : "f"(0.0f), "f"(x));
    return (uint8_t)r;   // low byte = second source
}

// ---- kernel 0: zero accumulators ----
__global__ void sg_zero_kernel() {
    int i = blockIdx.x * blockDim.x + threadIdx.x;
    if (i < CV * CN) g_denom[i] = 0.0f;
    if (i == 0) g_loss = 0.0;
}

// ---- kernel 1: L2-normalize rows -> fp8 (main) + fp16 (finalize) ----
__global__ void sg_normalize_kernel(const float* __restrict__ Hc,
                                    const float* __restrict__ Hv) {
    int row = blockIdx.x;
    const float* src;
    uint8_t* dst8;
    __half* dst16;
    float scale;
    if (row < CN) {
        src = Hc + (size_t)row * CD;
        dst8 = g_Hc8 + (size_t)row * CD;
        dst16 = g_Hc16 + (size_t)row * CD;
        scale = (float)K2LOG2E;
    } else {
        src = Hv + (size_t)(row - CN) * CD;
        dst8 = g_Hv8 + (size_t)(row - CN) * CD;
        dst16 = g_Hv16 + (size_t)(row - CN) * CD;
        scale = 1.0f;
    }
    int t = threadIdx.x;  // 128 threads
    float x = src[t];
    float ss = x * x;
#pragma unroll
    for (int o = 16; o > 0; o >>= 1) ss += __shfl_xor_sync(0xffffffffu, ss, o);
    __shared__ float ws[4];
    if ((t & 31) == 0) ws[t >> 5] = ss;
    __syncthreads();
    float tot = ws[0] + ws[1] + ws[2] + ws[3];
    float invn = scale / fmaxf(sqrtf(tot), 1e-12f);
    float y = x * invn;
    dst8[t] = f2e4m3(y);
    dst16[t] = __float2half_rn(y);
}

// ---- smem tile loaders (256 threads, fp8, 16B chunks) ----
__device__ __forceinline__ void load_A(uint32_t sb, int n0, int t) {
#pragma unroll
    for (int k = 0; k < 4; k++) {
        int q = t + k * 256;            // 0..1023
        int r = q >> 3;                 // row 0..127 (8 chunks/row)
        int c = q & 7;
        cp_async16(sb + A_OFF + r * RS8 + c * 16,
                   g_Hc8 + (size_t)(n0 + r) * CD + c * 16);
    }
}
__device__ __forceinline__ void load_B(uint32_t sb, int buf, int m0, int t) {
    uint32_t base = sb + B_OFF + buf * B_BUF_BYTES;
#pragma unroll
    for (int k = 0; k < 6; k++) {
        int Q = t + k * 256;            // 0..1535
        int v = Q >> 9;                 // view (512 chunks per view)
        int qq = Q & 511;
        int r = qq >> 3;                // row 0..63
        int c = qq & 7;
        cp_async16(base + v * B_VIEW_BYTES + r * RS8 + c * 16,
                   g_Hv8 + ((size_t)v * CN + (m0 + r)) * CD + c * 16);
    }
}

// ---- kernel 2: FP8 MMA fused GEMM + exp + weighted denom ----
// 256 threads = 8 warps: grid 4(n) x 2(m); each warp 32n x 32m, K=128 in 4 k32 steps.
__global__ __launch_bounds__(256, 1) void sg_main_kernel(const float* __restrict__ S) {
    extern __shared__ char smem[];
    uint32_t sb = smem_u32(smem);
    const int t = threadIdx.x;
    const int lane = t & 31;
    const int wid = t >> 5;
    const int wn = wid >> 1;     // 0..3 : 32-row group
    const int wm = wid & 1;      // 0..1 : 32-col half
    const int grp = lane >> 2;   // 0..7
    const int qd = lane & 3;     // 0..3

    const int job0 = (int)(((long long)blockIdx.x * TOTAL_JOBS) / gridDim.x);
    const int job1 = (int)(((long long)(blockIdx.x + 1) * TOTAL_JOBS) / gridDim.x);

    int j = job0;
    while (j < job1) {
        const int nt = j >> 7;
        const int mt0 = j & 127;
        const int jend = min(job1, (nt + 1) << 7);
        const int nTi = jend - j;
        const int n0 = nt * TM;

        __syncthreads();  // previous segment fully done before overwriting smem
        load_A(sb, n0, t);
        load_B(sb, 0, mt0 * TN, t);
        CP_COMMIT();
        if (nTi > 1) { load_B(sb, 1, (mt0 + 1) * TN, t); }
        CP_COMMIT();

        uint32_t af[4][2][4];   // [kstep][mi][reg]
        float denomAcc[CV][2][2];
#pragma unroll
        for (int v = 0; v < CV; v++)
#pragma unroll
            for (int a = 0; a < 2; a++)
#pragma unroll
                for (int b = 0; b < 2; b++) denomAcc[v][a][b] = 0.0f;

        const int row_base = n0 + wn * 32 + grp;
        const int col_base = wm * 32 + 2 * qd;

        int buf = 0;
        for (int i = 0; i < nTi; i++) {
            if (i + 1 < nTi) CP_WAIT1(); else CP_WAIT0();
            __syncthreads();  // B(i) visible; compute(i-1) done everywhere

            int nbuf = buf + 2; if (nbuf >= 3) nbuf -= 3;
            if (i + 2 < nTi) { load_B(sb, nbuf, (mt0 + i + 2) * TN, t); CP_COMMIT(); }

            if (i == 0) {
                // A fragments (fp8 m16n8k32 layout) straight from smem, conflict-free
                const char* ab = smem + A_OFF + (size_t)(wn * 32 + grp) * RS8 + 4 * qd;
#pragma unroll
                for (int ks = 0; ks < 4; ks++)
#pragma unroll
                    for (int mi = 0; mi < 2; mi++) {
                        const char* p = ab + mi * 16 * RS8 + ks * 32;
                        af[ks][mi][0] = *reinterpret_cast<const uint32_t*>(p);
                        af[ks][mi][1] = *reinterpret_cast<const uint32_t*>(p + 8 * RS8);
                        af[ks][mi][2] = *reinterpret_cast<const uint32_t*>(p + 16);
                        af[ks][mi][3] = *reinterpret_cast<const uint32_t*>(p + 8 * RS8 + 16);
                    }
            }

            const int m0 = (mt0 + i) * TN;
            // (1 - S) weights: [mi][row-octet][ni] float2
            float2 wv[2][2][4];
#pragma unroll
            for (int mi = 0; mi < 2; mi++)
#pragma unroll
                for (int d8 = 0; d8 < 2; d8++) {
                    const float* rp = S + (size_t)(row_base + mi * 16 + 8 * d8) * CN +
                                      (m0 + col_base);
#pragma unroll
                    for (int ni = 0; ni < 4; ni++) {
                        float2 x = *reinterpret_cast<const float2*>(rp + ni * 8);
                        wv[mi][d8][ni] = make_float2(1.0f - x.x, 1.0f - x.y);
                    }
                }

#pragma unroll
            for (int v = 0; v < CV; v++) {
                float acc[2][4][4];
#pragma unroll
                for (int mi = 0; mi < 2; mi++)
#pragma unroll
                    for (int ni = 0; ni < 4; ni++)
#pragma unroll
                        for (int c = 0; c < 4; c++) acc[mi][ni][c] = 0.0f;

                const char* bb = smem + B_OFF + buf * B_BUF_BYTES + v * B_VIEW_BYTES +
                                 (size_t)(wm * 32 + grp) * RS8 + 4 * qd;
#pragma unroll
                for (int ks = 0; ks < 4; ks++) {
#pragma unroll
                    for (int ni = 0; ni < 4; ni++) {
                        uint32_t b0 = *reinterpret_cast<const uint32_t*>(bb + ni * 8 * RS8 + ks * 32);
                        uint32_t b1 = *reinterpret_cast<const uint32_t*>(bb + ni * 8 * RS8 + ks * 32 + 16);
                        mma_fp8(acc[0][ni], af[ks][0], b0, b1);
                        mma_fp8(acc[1][ni], af[ks][1], b0, b1);
                    }
                }
                // epilogue: acc = log2(exp(2*sim)) (A pre-scaled); denom += w * 2^acc
#pragma unroll
                for (int mi = 0; mi < 2; mi++) {
                    float d0 = 0.0f, d1 = 0.0f;
#pragma unroll
                    for (int ni = 0; ni < 4; ni++) {
                        float2 w0 = wv[mi][0][ni];
                        float2 w1 = wv[mi][1][ni];
                        d0 = fmaf(w0.x, ex2f(acc[mi][ni][0]), d0);
                        d0 = fmaf(w0.y, ex2f(acc[mi][ni][1]), d0);
                        d1 = fmaf(w1.x, ex2f(acc[mi][ni][2]), d1);
                        d1 = fmaf(w1.y, ex2f(acc[mi][ni][3]), d1);
                    }
                    denomAcc[v][mi][0] += d0;
                    denomAcc[v][mi][1] += d1;
                }
            }
            buf++; if (buf >= 3) buf -= 3;
        }

        // flush denominators (reduce over qd = distinct col groups)
#pragma unroll
        for (int v = 0; v < CV; v++)
#pragma unroll
            for (int mi = 0; mi < 2; mi++)
#pragma unroll
                for (int d8 = 0; d8 < 2; d8++) {
                    float val = denomAcc[v][mi][d8];
                    val += __shfl_xor_sync(0xffffffffu, val, 1);
                    val += __shfl_xor_sync(0xffffffffu, val, 2);
                    if (qd == 0)
                        atomicAdd(&g_denom[v * CN + row_base + mi * 16 + 8 * d8], val);
                }
        j = jend;
    }
}

// ---- kernel 3: positives + loss reduction (fp16 path, Hc pre-scaled by 2/ln2) ----
__global__ void sg_finalize_kernel() {
    int gwarp = (blockIdx.x * blockDim.x + threadIdx.x) >> 5;
    int lane = threadIdx.x & 31;
    int v = gwarp / CN;
    int n = gwarp % CN;
    const __half* a = g_Hc16 + (size_t)n * CD;
    const __half* b = g_Hv16 + (size_t)v * CN * CD + (size_t)n * CD;
    float s = 0.0f;
#pragma unroll
    for (int k = 0; k < CD / 32; k++)
        s += __half2float(a[lane + 32 * k]) * __half2float(b[lane + 32 * k]);
#pragma unroll
    for (int o = 16; o > 0; o >>= 1) s += __shfl_xor_sync(0xffffffffu, s, o);

    __shared__ double part[8];
    if (lane == 0) {
        float den = fmaxf(g_denom[gwarp], 1e-9f);
        part[threadIdx.x >> 5] = (double)(logf(den) - s * LN2F);
    }
    __syncthreads();
    if (threadIdx.x == 0) {
        double bs = 0.0;
#pragma unroll
        for (int w = 0; w < 8; w++) bs += part[w];
        atomicAdd(&g_loss, bs);
    }
}

// ---- kernel 4: write scalar output ----
__global__ void sg_writeout_kernel(float* out) {
    out[0] = (float)(g_loss / (double)((long long)CN * CV));
}

extern "C" void kernel_launch(void* const* d_in, const int* in_sizes, int n_in,
                              void* d_out, int out_size) {
    const float* Hc = (const float*)d_in[0];
    const float* S = (const float*)d_in[1];
    const float* Hv = (const float*)d_in[2];
    float* out = (float*)d_out;

    int nsm = 148;
    cudaDeviceGetAttribute(&nsm, cudaDevAttrMultiProcessorCount, 0);

    cudaFuncSetAttribute(sg_main_kernel, cudaFuncAttributeMaxDynamicSharedMemorySize,
                         SMEM_TOTAL);

    sg_zero_kernel<<<(CV * CN + 255) / 256, 256>>>();
    sg_normalize_kernel<<<(CV + 1) * CN, 128>>>(Hc, Hv);
    sg_main_kernel<<<nsm, 256, SMEM_TOTAL>>>(S);
    sg_finalize_kernel<<<(CV * CN) / 8, 256>>>();
    sg_writeout_kernel<<<1, 1>>>(out);
}

// round 7
// speedup vs baseline: 1.2316x; 1.2316x over previous
#include <cuda_runtime.h>
#include <cuda_fp16.h>
#include <math.h>
#include <cstdint>

#define CN 8192
#define CD 128
#define CV 3

#define TM 128            // n rows per CTA tile
#define TN 64             // m cols per tile
#define NTILES (CN / TM)  // 64
#define MTILES (CN / TN)  // 128
#define TOTAL_JOBS (NTILES * MTILES)  // 8192

#define RSTRIDE 272       // padded row stride (bytes): conflict-free ldmatrix
#define A_OFF 0
#define A_BYTES (TM * RSTRIDE)                 // 34816
#define B_OFF A_BYTES
#define B_VIEW_BYTES (TN * RSTRIDE)            // 17408
#define B_BUF_BYTES (CV * B_VIEW_BYTES)        // 52224
#define NBUF 3
#define SMEM_TOTAL (B_OFF + NBUF * B_BUF_BYTES)  // 191488

#define K2LOG2E 2.8853900817779268  /* 2/ln2 : exp(2*sim) = 2^(sim*K2) */
#define LN2F 0.6931471805599453f

// ---- device scratch ----
__device__ __align__(256) __half g_Hc16[CN * CD];   // pre-scaled by 2/ln2
__device__ __align__(256) __half g_Hv16[CV * CN * CD];
__device__ __align__(256) float g_denom[CV * CN];
__device__ double g_loss;
__device__ unsigned int g_done;   // finalize last-block counter (reset each run)

// ---------------- helpers ----------------
__device__ __forceinline__ uint32_t smem_u32(const void* p) {
    uint32_t a;
    asm("{ .reg .u64 t; cvta.to.shared.u64 t, %1; cvt.u32.u64 %0, t; }" : "=r"(a) : "l"(p));
    return a;
}
__device__ __forceinline__ void cp_async16(uint32_t dst, const void* src) {
    asm volatile("cp.async.cg.shared.global [%0], [%1], 16;" :: "r"(dst), "l"(src));
}
#define CP_COMMIT() asm volatile("cp.async.commit_group;" ::: "memory")
#define CP_WAIT0()  asm volatile("cp.async.wait_group 0;" ::: "memory")
#define CP_WAIT1()  asm volatile("cp.async.wait_group 1;" ::: "memory")

__device__ __forceinline__ void ldm4(uint32_t* r, uint32_t a) {
    asm volatile("ldmatrix.sync.aligned.m8n8.x4.shared.b16 {%0,%1,%2,%3}, [%4];"
                 : "=r"(r[0]), "=r"(r[1]), "=r"(r[2]), "=r"(r[3]) : "r"(a));
}
__device__ __forceinline__ void mma16816h(uint32_t* c, const uint32_t* a, uint32_t b0, uint32_t b1) {
    asm volatile(
        "mma.sync.aligned.m16n8k16.row.col.f16.f16.f16.f16 "
        "{%0,%1}, {%2,%3,%4,%5}, {%6,%7}, {%0,%1};"
        : "+r"(c[0]), "+r"(c[1])
        : "r"(a[0]), "r"(a[1]), "r"(a[2]), "r"(a[3]), "r"(b0), "r"(b1));
}
__device__ __forceinline__ __half2 ex2h2(uint32_t x) {
    uint32_t r;
    asm("ex2.approx.f16x2 %0, %1;" : "=r"(r) : "r"(x));
    return *reinterpret_cast<__half2*>(&r);
}

// ---- kernel 1: L2-normalize rows -> fp16 (Hc pre-scaled by 2/ln2); also zeros accumulators ----
// 512 threads, 4 rows per block; grid = (CV+1)*CN/4 = 8192 blocks
__global__ __launch_bounds__(512) void sg_normalize_kernel(const float* __restrict__ Hc,
                                                           const float* __restrict__ Hv) {
    int row = blockIdx.x * 4 + (threadIdx.x >> 7);
    int t = threadIdx.x & 127;

    // fused accumulator zeroing (first 192 blocks cover CV*CN = 24576 floats)
    if (blockIdx.x < (CV * CN) / 128) {
        if ((threadIdx.x >> 7) == 0) g_denom[blockIdx.x * 128 + t] = 0.0f;
        if (blockIdx.x == 0 && threadIdx.x == 0) { g_loss = 0.0; g_done = 0u; }
    }

    const float* src;
    __half* dst;
    float scale;
    if (row < CN) {
        src = Hc + (size_t)row * CD;
        dst = g_Hc16 + (size_t)row * CD;
        scale = (float)K2LOG2E;
    } else {
        src = Hv + (size_t)(row - CN) * CD;
        dst = g_Hv16 + (size_t)(row - CN) * CD;
        scale = 1.0f;
    }
    float x = src[t];
    float ss = x * x;
#pragma unroll
    for (int o = 16; o > 0; o >>= 1) ss += __shfl_xor_sync(0xffffffffu, ss, o);
    __shared__ float ws[16];
    if ((t & 31) == 0) ws[threadIdx.x >> 5] = ss;
    __syncthreads();
    int wg = (threadIdx.x >> 7) * 4;
    float tot = ws[wg] + ws[wg + 1] + ws[wg + 2] + ws[wg + 3];
    float invn = scale / fmaxf(sqrtf(tot), 1e-12f);
    dst[t] = __float2half_rn(x * invn);
}

// ---- smem tile loaders ----
__device__ __forceinline__ void load_A(uint32_t sb, int n0, int t) {
#pragma unroll
    for (int k = 0; k < 8; k++) {
        int q = t + k * 256;
        int r = q >> 4;
        int c = q & 15;
        cp_async16(sb + A_OFF + r * RSTRIDE + c * 16,
                   g_Hc16 + (size_t)(n0 + r) * CD + c * 8);
    }
}
__device__ __forceinline__ void load_B(uint32_t sb, int buf, int m0, int t) {
    uint32_t base = sb + B_OFF + buf * B_BUF_BYTES;
#pragma unroll
    for (int k = 0; k < 12; k++) {
        int Q = t + k * 256;
        int v = Q >> 10;
        int qq = Q & 1023;
        int r = qq >> 4;
        int c = qq & 15;
        cp_async16(base + v * B_VIEW_BYTES + r * RSTRIDE + c * 16,
                   g_Hv16 + ((size_t)v * CN + (m0 + r)) * CD + c * 8);
    }
}

// ---- kernel 2: HMMA(f16-acc) fused GEMM + exp + weighted denom (round-4 winner, verbatim) ----
__global__ __launch_bounds__(256, 1) void sg_main_kernel(const float* __restrict__ S) {
    extern __shared__ char smem[];
    uint32_t sb = smem_u32(smem);
    const int t = threadIdx.x;
    const int lane = t & 31;
    const int wid = t >> 5;
    const int wn = wid >> 1;     // 0..3 : n quarter
    const int wm = wid & 1;      // 0..1 : m half
    const int g = lane >> 3;
    const int lr = lane & 7;
    const uint32_t aoff = (uint32_t)(((g & 1) * 8 + lr) * RSTRIDE + (g >> 1) * 16);
    const uint32_t boff = (uint32_t)(((g >> 1) * 8 + lr) * RSTRIDE + (g & 1) * 16);

    const int job0 = (int)(((long long)blockIdx.x * TOTAL_JOBS) / gridDim.x);
    const int job1 = (int)(((long long)(blockIdx.x + 1) * TOTAL_JOBS) / gridDim.x);

    int j = job0;
    while (j < job1) {
        const int nt = j >> 7;
        const int mt0 = j & 127;
        const int jend = min(job1, (nt + 1) << 7);
        const int nTi = jend - j;
        const int n0 = nt * TM;

        __syncthreads();  // previous segment fully done before overwriting smem
        load_A(sb, n0, t);
        load_B(sb, 0, mt0 * TN, t);
        CP_COMMIT();
        if (nTi > 1) { load_B(sb, 1, (mt0 + 1) * TN, t); }
        CP_COMMIT();

        uint32_t af[8][2][4];
        float denomAcc[CV][2][2];
#pragma unroll
        for (int v = 0; v < CV; v++)
#pragma unroll
            for (int a = 0; a < 2; a++)
#pragma unroll
                for (int b = 0; b < 2; b++) denomAcc[v][a][b] = 0.0f;

        const int row_base = n0 + wn * 32 + (lane >> 2);
        const int col_base = wm * 32 + 2 * (lane & 3);

        int buf = 0;
        for (int i = 0; i < nTi; i++) {
            if (i + 1 < nTi) CP_WAIT1(); else CP_WAIT0();
            __syncthreads();  // B(i) visible; compute(i-1) done everywhere

            int nbuf = buf + 2; if (nbuf >= 3) nbuf -= 3;
            if (i + 2 < nTi) { load_B(sb, nbuf, (mt0 + i + 2) * TN, t); CP_COMMIT(); }

            if (i == 0) {
                uint32_t abase = sb + A_OFF + (uint32_t)(wn * 32) * RSTRIDE + aoff;
#pragma unroll
                for (int ks = 0; ks < 8; ks++)
#pragma unroll
                    for (int mi = 0; mi < 2; mi++)
                        ldm4(af[ks][mi], abase + mi * 16 * RSTRIDE + ks * 32);
            }

            const int m0 = (mt0 + i) * TN;
            __half2 wv[2][2][4];  // [mi][row-octet][ni]
#pragma unroll
            for (int mi = 0; mi < 2; mi++)
#pragma unroll
                for (int d8 = 0; d8 < 2; d8++) {
                    const float* rp = S + (size_t)(row_base + mi * 16 + 8 * d8) * CN +
                                      (m0 + col_base);
#pragma unroll
                    for (int ni = 0; ni < 4; ni++) {
                        float2 x = *reinterpret_cast<const float2*>(rp + ni * 8);
                        wv[mi][d8][ni] = __floats2half2_rn(1.0f - x.x, 1.0f - x.y);
                    }
                }

#pragma unroll
            for (int v = 0; v < CV; v++) {
                uint32_t acc[2][4][2];
#pragma unroll
                for (int mi = 0; mi < 2; mi++)
#pragma unroll
                    for (int ni = 0; ni < 4; ni++) {
                        acc[mi][ni][0] = 0u; acc[mi][ni][1] = 0u;
                    }

                uint32_t bbase = sb + B_OFF + buf * B_BUF_BYTES + v * B_VIEW_BYTES +
                                 (uint32_t)(wm * 32) * RSTRIDE + boff;
#pragma unroll
                for (int ks = 0; ks < 8; ks++) {
                    uint32_t bf0[4], bf1[4];
                    ldm4(bf0, bbase + ks * 32);
                    ldm4(bf1, bbase + 16 * RSTRIDE + ks * 32);
#pragma unroll
                    for (int mi = 0; mi < 2; mi++) {
                        mma16816h(acc[mi][0], af[ks][mi], bf0[0], bf0[1]);
                        mma16816h(acc[mi][1], af[ks][mi], bf0[2], bf0[3]);
                        mma16816h(acc[mi][2], af[ks][mi], bf1[0], bf1[1]);
                        mma16816h(acc[mi][3], af[ks][mi], bf1[2], bf1[3]);
                    }
                }
#pragma unroll
                for (int mi = 0; mi < 2; mi++) {
                    __half2 h0 = __floats2half2_rn(0.0f, 0.0f);
                    __half2 h1 = h0;
#pragma unroll
                    for (int ni = 0; ni < 4; ni++) {
                        h0 = __hfma2(wv[mi][0][ni], ex2h2(acc[mi][ni][0]), h0);
                        h1 = __hfma2(wv[mi][1][ni], ex2h2(acc[mi][ni][1]), h1);
                    }
                    float2 f0 = __half22float2(h0);
                    float2 f1 = __half22float2(h1);
                    denomAcc[v][mi][0] += f0.x + f0.y;
                    denomAcc[v][mi][1] += f1.x + f1.y;
                }
            }
            buf++; if (buf >= 3) buf -= 3;
        }

#pragma unroll
        for (int v = 0; v < CV; v++)
#pragma unroll
            for (int mi = 0; mi < 2; mi++)
#pragma unroll
                for (int d8 = 0; d8 < 2; d8++) {
                    float val = denomAcc[v][mi][d8];
                    val += __shfl_xor_sync(0xffffffffu, val, 1);
                    val += __shfl_xor_sync(0xffffffffu, val, 2);
                    if ((lane & 3) == 0)
                        atomicAdd(&g_denom[v * CN + row_base + mi * 16 + 8 * d8], val);
                }
        j = jend;
    }
}

// ---- kernel 3: positives + loss reduction + fused writeout ----
// g_Hc16 pre-scaled by 2/ln2 -> positive = (scaled dot) * ln2
// vectorized: each lane loads 4 halfs (8B) per array; last finished block writes out.
#define FIN_BLOCKS ((CV * CN) / 8)
__global__ void sg_finalize_kernel(float* __restrict__ out) {
    int gwarp = (blockIdx.x * blockDim.x + threadIdx.x) >> 5;
    int lane = threadIdx.x & 31;
    int v = gwarp / CN;
    int n = gwarp % CN;
    const uint2* a = reinterpret_cast<const uint2*>(g_Hc16 + (size_t)n * CD) + lane;
    const uint2* b = reinterpret_cast<const uint2*>(g_Hv16 + ((size_t)v * CN + n) * CD) + lane;
    uint2 av = *a, bv = *b;
    __half2 p = __hmul2(*reinterpret_cast<__half2*>(&av.x), *reinterpret_cast<__half2*>(&bv.x));
    p = __hfma2(*reinterpret_cast<__half2*>(&av.y), *reinterpret_cast<__half2*>(&bv.y), p);
    float s = __half2float(p.x) + __half2float(p.y);
#pragma unroll
    for (int o = 16; o > 0; o >>= 1) s += __shfl_xor_sync(0xffffffffu, s, o);

    __shared__ double part[8];
    if (lane == 0) {
        float den = fmaxf(g_denom[gwarp], 1e-9f);
        part[threadIdx.x >> 5] = (double)(logf(den) - s * LN2F);
    }
    __syncthreads();
    if (threadIdx.x == 0) {
        double bs = 0.0;
#pragma unroll
        for (int w = 0; w < 8; w++) bs += part[w];
        atomicAdd(&g_loss, bs);
        __threadfence();
        unsigned int done = atomicAdd(&g_done, 1u);
        if (done == FIN_BLOCKS - 1) {
            // last block: publish result and reset counter for graph replay
            out[0] = (float)(g_loss / (double)((long long)CN * CV));
            g_done = 0u;
        }
    }
}

extern "C" void kernel_launch(void* const* d_in, const int* in_sizes, int n_in,
                              void* d_out, int out_size) {
    const float* Hc = (const float*)d_in[0];
    const float* S = (const float*)d_in[1];
    const float* Hv = (const float*)d_in[2];
    float* out = (float*)d_out;

    int nsm = 148;
    cudaDeviceGetAttribute(&nsm, cudaDevAttrMultiProcessorCount, 0);

    cudaFuncSetAttribute(sg_main_kernel, cudaFuncAttributeMaxDynamicSharedMemorySize,
                         SMEM_TOTAL);

    sg_normalize_kernel<<<(CV + 1) * CN / 4, 512>>>(Hc, Hv);
    sg_main_kernel<<<nsm, 256, SMEM_TOTAL>>>(S);
    sg_finalize_kernel<<<FIN_BLOCKS, 256>>>(out);
}

// round 8
// speedup vs baseline: 1.3246x; 1.0755x over previous
#include <cuda_runtime.h>
#include <cuda_fp16.h>
#include <math.h>
#include <cstdint>

#define CN 8192
#define CD 128
#define CV 3

#define TM 128            // n rows per CTA tile
#define TN 64             // m cols per tile
#define NTILES (CN / TM)  // 64
#define MTILES (CN / TN)  // 128
#define TOTAL_JOBS (NTILES * MTILES)  // 8192

#define RSTRIDE 272       // padded row stride (bytes): conflict-free ldmatrix
#define A_OFF 0
#define A_BYTES (TM * RSTRIDE)                 // 34816
#define B_OFF A_BYTES
#define B_VIEW_BYTES (TN * RSTRIDE)            // 17408
#define B_BUF_BYTES (CV * B_VIEW_BYTES)        // 52224
#define NBUF 3
#define SMEM_TOTAL (B_OFF + NBUF * B_BUF_BYTES)  // 191488

#define K2LOG2E 2.8853900817779268  /* 2/ln2 : exp(2*sim) = 2^(sim*K2) */
#define LN2F 0.6931471805599453f

// ---- device scratch ----
__device__ __align__(256) __half g_Hc16[CN * CD];   // pre-scaled by 2/ln2
__device__ __align__(256) __half g_Hv16[CV * CN * CD];
__device__ __align__(256) float g_denom[CV * CN];
__device__ __align__(256) float g_pos[CV * CN];     // positives (diag), written by main
__device__ double g_loss;
__device__ unsigned int g_done;

// ---------------- helpers ----------------
__device__ __forceinline__ uint32_t smem_u32(const void* p) {
    uint32_t a;
    asm("{ .reg .u64 t; cvta.to.shared.u64 t, %1; cvt.u32.u64 %0, t; }" : "=r"(a) : "l"(p));
    return a;
}
__device__ __forceinline__ void cp_async16(uint32_t dst, const void* src) {
    asm volatile("cp.async.cg.shared.global [%0], [%1], 16;" :: "r"(dst), "l"(src));
}
#define CP_COMMIT() asm volatile("cp.async.commit_group;" ::: "memory")
#define CP_WAIT0()  asm volatile("cp.async.wait_group 0;" ::: "memory")
#define CP_WAIT1()  asm volatile("cp.async.wait_group 1;" ::: "memory")

__device__ __forceinline__ void ldm4(uint32_t* r, uint32_t a) {
    asm volatile("ldmatrix.sync.aligned.m8n8.x4.shared.b16 {%0,%1,%2,%3}, [%4];"
                 : "=r"(r[0]), "=r"(r[1]), "=r"(r[2]), "=r"(r[3]) : "r"(a));
}
__device__ __forceinline__ void mma16816h(uint32_t* c, const uint32_t* a, uint32_t b0, uint32_t b1) {
    asm volatile(
        "mma.sync.aligned.m16n8k16.row.col.f16.f16.f16.f16 "
        "{%0,%1}, {%2,%3,%4,%5}, {%6,%7}, {%0,%1};"
        : "+r"(c[0]), "+r"(c[1])
        : "r"(a[0]), "r"(a[1]), "r"(a[2]), "r"(a[3]), "r"(b0), "r"(b1));
}
__device__ __forceinline__ __half2 ex2h2(uint32_t x) {
    uint32_t r;
    asm("ex2.approx.f16x2 %0, %1;" : "=r"(r) : "r"(x));
    return *reinterpret_cast<__half2*>(&r);
}

// ---- kernel 1: L2-normalize, one warp per row, float4 loads; fused zeroing ----
// 256 threads = 8 warps/block; grid = (CV+1)*CN/8 = 4096 blocks
__global__ __launch_bounds__(256) void sg_normalize_kernel(const float* __restrict__ Hc,
                                                           const float* __restrict__ Hv) {
    // fused zero of g_denom (96 blocks x 256 = 24576) + scalars
    if (blockIdx.x < (CV * CN) / 256) {
        g_denom[blockIdx.x * 256 + threadIdx.x] = 0.0f;
        if (blockIdx.x == 0 && threadIdx.x == 0) { g_loss = 0.0; g_done = 0u; }
    }

    int row = blockIdx.x * 8 + (threadIdx.x >> 5);   // 0 .. 32767
    int lane = threadIdx.x & 31;
    const float* src;
    __half* dst;
    float scale;
    if (row < CN) {
        src = Hc + (size_t)row * CD;
        dst = g_Hc16 + (size_t)row * CD;
        scale = (float)K2LOG2E;
    } else {
        src = Hv + (size_t)(row - CN) * CD;
        dst = g_Hv16 + (size_t)(row - CN) * CD;
        scale = 1.0f;
    }
    float4 x = reinterpret_cast<const float4*>(src)[lane];
    float ss = x.x * x.x + x.y * x.y + x.z * x.z + x.w * x.w;
#pragma unroll
    for (int o = 16; o > 0; o >>= 1) ss += __shfl_xor_sync(0xffffffffu, ss, o);
    float invn = scale / fmaxf(sqrtf(ss), 1e-12f);
    __half2 h0 = __floats2half2_rn(x.x * invn, x.y * invn);
    __half2 h1 = __floats2half2_rn(x.z * invn, x.w * invn);
    uint2 u;
    u.x = *reinterpret_cast<uint32_t*>(&h0);
    u.y = *reinterpret_cast<uint32_t*>(&h1);
    reinterpret_cast<uint2*>(dst)[lane] = u;
}

// ---- smem tile loaders ----
__device__ __forceinline__ void load_A(uint32_t sb, int n0, int t) {
#pragma unroll
    for (int k = 0; k < 8; k++) {
        int q = t + k * 256;
        int r = q >> 4;
        int c = q & 15;
        cp_async16(sb + A_OFF + r * RSTRIDE + c * 16,
                   g_Hc16 + (size_t)(n0 + r) * CD + c * 8);
    }
}
__device__ __forceinline__ void load_B(uint32_t sb, int buf, int m0, int t) {
    uint32_t base = sb + B_OFF + buf * B_BUF_BYTES;
#pragma unroll
    for (int k = 0; k < 12; k++) {
        int Q = t + k * 256;
        int v = Q >> 10;
        int qq = Q & 1023;
        int r = qq >> 4;
        int c = qq & 15;
        cp_async16(base + v * B_VIEW_BYTES + r * RSTRIDE + c * 16,
                   g_Hv16 + ((size_t)v * CN + (m0 + r)) * CD + c * 8);
    }
}

// ---- kernel 2: HMMA(f16-acc) fused GEMM + exp + weighted denom + diag positives ----
__global__ __launch_bounds__(256, 1) void sg_main_kernel(const float* __restrict__ S) {
    extern __shared__ char smem[];
    uint32_t sb = smem_u32(smem);
    const int t = threadIdx.x;
    const int lane = t & 31;
    const int wid = t >> 5;
    const int wn = wid >> 1;     // 0..3 : n quarter
    const int wm = wid & 1;      // 0..1 : m half
    const int g = lane >> 3;
    const int lr = lane & 7;
    const uint32_t aoff = (uint32_t)(((g & 1) * 8 + lr) * RSTRIDE + (g >> 1) * 16);
    const uint32_t boff = (uint32_t)(((g >> 1) * 8 + lr) * RSTRIDE + (g & 1) * 16);

    const int job0 = (int)(((long long)blockIdx.x * TOTAL_JOBS) / gridDim.x);
    const int job1 = (int)(((long long)(blockIdx.x + 1) * TOTAL_JOBS) / gridDim.x);

    int j = job0;
    while (j < job1) {
        const int nt = j >> 7;
        const int mt0 = j & 127;
        const int jend = min(job1, (nt + 1) << 7);
        const int nTi = jend - j;
        const int n0 = nt * TM;

        __syncthreads();  // previous segment fully done before overwriting smem
        load_A(sb, n0, t);
        load_B(sb, 0, mt0 * TN, t);
        CP_COMMIT();
        if (nTi > 1) { load_B(sb, 1, (mt0 + 1) * TN, t); }
        CP_COMMIT();

        uint32_t af[8][2][4];
        float denomAcc[CV][2][2];
#pragma unroll
        for (int v = 0; v < CV; v++)
#pragma unroll
            for (int a = 0; a < 2; a++)
#pragma unroll
                for (int b = 0; b < 2; b++) denomAcc[v][a][b] = 0.0f;

        const int row_base = n0 + wn * 32 + (lane >> 2);
        const int col_base = wm * 32 + 2 * (lane & 3);

        int buf = 0;
        for (int i = 0; i < nTi; i++) {
            if (i + 1 < nTi) CP_WAIT1(); else CP_WAIT0();
            __syncthreads();  // B(i) visible; compute(i-1) done everywhere

            int nbuf = buf + 2; if (nbuf >= 3) nbuf -= 3;
            if (i + 2 < nTi) { load_B(sb, nbuf, (mt0 + i + 2) * TN, t); CP_COMMIT(); }

            if (i == 0) {
                uint32_t abase = sb + A_OFF + (uint32_t)(wn * 32) * RSTRIDE + aoff;
#pragma unroll
                for (int ks = 0; ks < 8; ks++)
#pragma unroll
                    for (int mi = 0; mi < 2; mi++)
                        ldm4(af[ks][mi], abase + mi * 16 * RSTRIDE + ks * 32);
            }

            const int mt = mt0 + i;
            const int m0 = mt * TN;
            const bool diag = ((mt >> 1) == nt);   // tile contains sim diagonal
            __half2 wv[2][2][4];  // [mi][row-octet][ni]
#pragma unroll
            for (int mi = 0; mi < 2; mi++)
#pragma unroll
                for (int d8 = 0; d8 < 2; d8++) {
                    const float* rp = S + (size_t)(row_base + mi * 16 + 8 * d8) * CN +
                                      (m0 + col_base);
#pragma unroll
                    for (int ni = 0; ni < 4; ni++) {
                        float2 x = *reinterpret_cast<const float2*>(rp + ni * 8);
                        wv[mi][d8][ni] = __floats2half2_rn(1.0f - x.x, 1.0f - x.y);
                    }
                }

#pragma unroll
            for (int v = 0; v < CV; v++) {
                uint32_t acc[2][4][2];
#pragma unroll
                for (int mi = 0; mi < 2; mi++)
#pragma unroll
                    for (int ni = 0; ni < 4; ni++) {
                        acc[mi][ni][0] = 0u; acc[mi][ni][1] = 0u;
                    }

                uint32_t bbase = sb + B_OFF + buf * B_BUF_BYTES + v * B_VIEW_BYTES +
                                 (uint32_t)(wm * 32) * RSTRIDE + boff;
#pragma unroll
                for (int ks = 0; ks < 8; ks++) {
                    uint32_t bf0[4], bf1[4];
                    ldm4(bf0, bbase + ks * 32);
                    ldm4(bf1, bbase + 16 * RSTRIDE + ks * 32);
#pragma unroll
                    for (int mi = 0; mi < 2; mi++) {
                        mma16816h(acc[mi][0], af[ks][mi], bf0[0], bf0[1]);
                        mma16816h(acc[mi][1], af[ks][mi], bf0[2], bf0[3]);
                        mma16816h(acc[mi][2], af[ks][mi], bf1[0], bf1[1]);
                        mma16816h(acc[mi][3], af[ks][mi], bf1[2], bf1[3]);
                    }
                }

                if (diag) {
                    // extract positives: unique owner per diagonal element
#pragma unroll
                    for (int mi = 0; mi < 2; mi++)
#pragma unroll
                        for (int ni = 0; ni < 4; ni++)
#pragma unroll
                            for (int oct = 0; oct < 2; oct++) {
                                int row = row_base + mi * 16 + 8 * oct;
                                int col = m0 + col_base + ni * 8;
                                __half2 h = *reinterpret_cast<__half2*>(&acc[mi][ni][oct]);
                                if (row == col)
                                    g_pos[v * CN + row] = __half2float(h.x) * LN2F;
                                else if (row == col + 1)
                                    g_pos[v * CN + row] = __half2float(h.y) * LN2F;
                            }
                }

#pragma unroll
                for (int mi = 0; mi < 2; mi++) {
                    __half2 h0 = __floats2half2_rn(0.0f, 0.0f);
                    __half2 h1 = h0;
#pragma unroll
                    for (int ni = 0; ni < 4; ni++) {
                        h0 = __hfma2(wv[mi][0][ni], ex2h2(acc[mi][ni][0]), h0);
                        h1 = __hfma2(wv[mi][1][ni], ex2h2(acc[mi][ni][1]), h1);
                    }
                    float2 f0 = __half22float2(h0);
                    float2 f1 = __half22float2(h1);
                    denomAcc[v][mi][0] += f0.x + f0.y;
                    denomAcc[v][mi][1] += f1.x + f1.y;
                }
            }
            buf++; if (buf >= 3) buf -= 3;
        }

#pragma unroll
        for (int v = 0; v < CV; v++)
#pragma unroll
            for (int mi = 0; mi < 2; mi++)
#pragma unroll
                for (int d8 = 0; d8 < 2; d8++) {
                    float val = denomAcc[v][mi][d8];
                    val += __shfl_xor_sync(0xffffffffu, val, 1);
                    val += __shfl_xor_sync(0xffffffffu, val, 2);
                    if ((lane & 3) == 0)
                        atomicAdd(&g_denom[v * CN + row_base + mi * 16 + 8 * d8], val);
                }
        j = jend;
    }
}

// ---- kernel 3: tiny loss reduction + writeout ----
#define FIN_BLOCKS ((CV * CN) / 256)   // 96
__global__ __launch_bounds__(256) void sg_finalize_kernel(float* __restrict__ out) {
    int i = blockIdx.x * 256 + threadIdx.x;
    float den = fmaxf(g_denom[i], 1e-9f);
    float val = logf(den) - g_pos[i];
#pragma unroll
    for (int o = 16; o > 0; o >>= 1) val += __shfl_xor_sync(0xffffffffu, val, o);
    __shared__ float part[8];
    if ((threadIdx.x & 31) == 0) part[threadIdx.x >> 5] = val;
    __syncthreads();
    if (threadIdx.x == 0) {
        float bs = 0.0f;
#pragma unroll
        for (int w = 0; w < 8; w++) bs += part[w];
        atomicAdd(&g_loss, (double)bs);
        __threadfence();
        unsigned int done = atomicAdd(&g_done, 1u);
        if (done == FIN_BLOCKS - 1) {
            out[0] = (float)(g_loss / (double)((long long)CN * CV));
            g_done = 0u;
        }
    }
}

extern "C" void kernel_launch(void* const* d_in, const int* in_sizes, int n_in,
                              void* d_out, int out_size) {
    const float* Hc = (const float*)d_in[0];
    const float* S = (const float*)d_in[1];
    const float* Hv = (const float*)d_in[2];
    float* out = (float*)d_out;

    int nsm = 148;
    cudaDeviceGetAttribute(&nsm, cudaDevAttrMultiProcessorCount, 0);

    cudaFuncSetAttribute(sg_main_kernel, cudaFuncAttributeMaxDynamicSharedMemorySize,
                         SMEM_TOTAL);

    sg_normalize_kernel<<<(CV + 1) * CN / 8, 256>>>(Hc, Hv);
    sg_main_kernel<<<nsm, 256, SMEM_TOTAL>>>(S);
    sg_finalize_kernel<<<FIN_BLOCKS, 256>>>(out);
}